// round 4
// baseline (speedup 1.0000x reference)
#include <cuda_runtime.h>

#define X 256
#define Y 256
#define Z 192
#define YX (X*Y)
#define NB 2
#define TX 128           // output tile width
#define TY 16            // output tile height
#define CW 34            // float4 columns incl 1-halo-col each side
#define ROWS 20          // rows incl y-halo 2 each side
#define NTH (CW*ROWS)    // 680 threads
#define ZCHUNKS 4
#define ZCK (Z/ZCHUNKS)  // 48

__device__ __forceinline__ float4 fmin4(float4 a, float4 b) {
    return make_float4(fminf(a.x,b.x), fminf(a.y,b.y), fminf(a.z,b.z), fminf(a.w,b.w));
}
__device__ __forceinline__ float4 fmax4(float4 a, float4 b) {
    return make_float4(fmaxf(a.x,b.x), fmaxf(a.y,b.y), fmaxf(a.z,b.z), fmaxf(a.w,b.w));
}
__device__ __forceinline__ float min3(float a, float b, float c) { return fminf(a, fminf(b, c)); }
__device__ __forceinline__ float max3(float a, float b, float c) { return fmaxf(a, fmaxf(b, c)); }

// out = relu(img - dilate3x3x3(erode3x3x3(img))), stride 1, pad 1.
// erode: min-pool pad +inf; dilate: max-pool pad -inf (domain mask on erode).
// Thread = one float4 x-column at one row (incl halo); z marched with register
// rings (img ring v0..v2, erode ring e0..e1). Per plane: ONE smem round per
// stage (store z-reduced plane + its edge scalars; read U/D float4 + 6 edge
// scalars; do y- and x-window in registers). 2 barriers/plane.
__global__ __launch_bounds__(NTH, 2)
void soft_skel_kernel(const float* __restrict__ img, float* __restrict__ out) {
    __shared__ float4 A[ROWS*CW];          // erode stage: z-min plane
    __shared__ float  ALE[ROWS*CW];        // A[.].w mirror (left-edge scalars)
    __shared__ float  ARE[ROWS*CW];        // A[.].x mirror (right-edge scalars)
    __shared__ float4 B[ROWS*CW];          // dilate stage: z-maxed erode plane
    __shared__ float  BLE[ROWS*CW];
    __shared__ float  BRE[ROWS*CW];

    const int tid = threadIdx.x;
    const int c   = tid % CW;
    const int iy  = tid / CW;
    const int bx0 = blockIdx.x * TX;
    const int by0 = blockIdx.y * TY;
    const int bz  = blockIdx.z;
    const int b   = bz / ZCHUNKS;
    const int z0  = (bz % ZCHUNKS) * ZCK;
    const int z1  = z0 + ZCK;

    const int gx0 = bx0 + c*4 - 4;                 // first x of this float4
    const int gy  = by0 + iy - 2;
    // float4 column is uniformly in or out of image in x (bx0 % 128 == 0, X=256)
    const bool inImg = (gx0 >= 0) && (gx0 < X) && (gy >= 0) && (gy < Y);
    const bool doOut = (iy >= 2) && (iy < 2+TY) && (c >= 1) && (c <= CW-2);

    // row bases (clamped; clamped-row results are garbage but never consumed)
    const int rC = iy*CW;
    const int rU = (iy > 0      ? iy-1 : 0     )*CW;
    const int rD = (iy < ROWS-1 ? iy+1 : ROWS-1)*CW;
    const int cL = (c > 0    ? c-1 : 0   );
    const int cR = (c < CW-1 ? c+1 : CW-1);
    const int own = rC + c, up = rU + c, dn = rD + c;

    const float PINF = __int_as_float(0x7f800000);
    const float NINF = __int_as_float(0xff800000);
    const float4 PI4 = make_float4(PINF,PINF,PINF,PINF);
    const float4 NI4 = make_float4(NINF,NINF,NINF,NINF);

    const long base = (long)b * Z * YX + (long)gy * X + gx0;
    const float* pIn = img + base + (long)(z0 - 1) * YX;   // next plane to load
    float*       pO  = out + base + (long)z0 * YX;

    // rings
    float4 v0 = PI4, v1 = PI4, v2;
    float4 e0 = NI4, e1 = NI4;

    v2 = (inImg && z0 >= 2) ? *(const float4*)(pIn - YX) : PI4;  // plane z0-2

    for (int zi = z0 - 2; zi <= z1 + 1; ++zi) {
        // ---- prefetch plane zi+1 (latency overlapped with this plane)
        float4 vn = PI4;
        {
            const int zn = zi + 1;
            if (inImg && (unsigned)zn < (unsigned)Z) vn = *(const float4*)pIn;
            pIn += YX;
        }

        // ================= erode stage (plane zc = zi-1) =================
        float4 zm = fmin4(v0, fmin4(v1, v2));           // z-window min
        A[own]   = zm;
        ALE[own] = zm.w;
        ARE[own] = zm.x;
        __syncthreads();

        float4 u = A[up];
        float4 d = A[dn];
        float y0 = min3(zm.x, u.x, d.x);
        float y1 = min3(zm.y, u.y, d.y);
        float y2 = min3(zm.z, u.z, d.z);
        float y3 = min3(zm.w, u.w, d.w);
        float lm = min3(ALE[rU+cL], ALE[rC+cL], ALE[rD+cL]);  // ymin at x-1
        float rm = min3(ARE[rU+cR], ARE[rC+cR], ARE[rD+cR]);  // ymin at x+4
        float4 ex;
        ex.x = min3(lm, y0, y1);
        ex.y = min3(y0, y1, y2);
        ex.z = min3(y1, y2, y3);
        ex.w = min3(y2, y3, rm);

        // domain mask for dilate padding (-inf outside image / z-range)
        const int zc = zi - 1;
        const bool vC = inImg && ((unsigned)zc < (unsigned)Z);
        float4 en;
        en.x = vC ? ex.x : NINF;
        en.y = vC ? ex.y : NINF;
        en.z = vC ? ex.z : NINF;
        en.w = vC ? ex.w : NINF;

        // ================= dilate-z (plane zo = zi-2), stage B ===========
        float4 dd = fmax4(e0, fmax4(e1, en));
        e0 = e1; e1 = en;

        B[own]   = dd;
        BLE[own] = dd.w;
        BRE[own] = dd.x;
        __syncthreads();

        // ================= dilate y+x and output ========================
        if (zi >= z0 + 2) {
            if (doOut) {
                float4 ub = B[up];
                float4 db = B[dn];
                float m0 = max3(dd.x, ub.x, db.x);
                float m1 = max3(dd.y, ub.y, db.y);
                float m2 = max3(dd.z, ub.z, db.z);
                float m3 = max3(dd.w, ub.w, db.w);
                float lmx = max3(BLE[rU+cL], BLE[rC+cL], BLE[rD+cL]);
                float rmx = max3(BRE[rU+cR], BRE[rC+cR], BRE[rD+cR]);
                float4 r;
                r.x = fmaxf(v0.x - max3(lmx, m0, m1), 0.0f);  // v0 = img plane zo
                r.y = fmaxf(v0.y - max3(m0, m1, m2), 0.0f);
                r.z = fmaxf(v0.z - max3(m1, m2, m3), 0.0f);
                r.w = fmaxf(v0.w - max3(m2, m3, rmx), 0.0f);
                *(float4*)pO = r;
            }
            pO += YX;
        }

        // ---- shift img ring
        v0 = v1; v1 = v2; v2 = vn;
    }
}

extern "C" void kernel_launch(void* const* d_in, const int* in_sizes, int n_in,
                              void* d_out, int out_size) {
    (void)in_sizes; (void)n_in; (void)out_size;
    const float* img = (const float*)d_in[0];
    float* out = (float*)d_out;
    dim3 grid(X / TX, Y / TY, NB * ZCHUNKS);
    soft_skel_kernel<<<grid, NTH>>>(img, out);
}

// round 5
// speedup vs baseline: 1.1123x; 1.1123x over previous
#include <cuda_runtime.h>

#define X 256
#define Y 256
#define Z 192
#define YX (X*Y)
#define NB 2
#define TX 64          // output tile width (elements)
#define TY 8           // output tile height
#define CW 34          // float2 columns = (TX+4)/2
#define CH 12          // rows = TY+4 (halo 2 each side)
#define NTH (CW*CH)    // 408 threads
#define ZCHUNKS 2
#define ZCK (Z/ZCHUNKS) /* 96 */

__device__ __forceinline__ float2 fmin2(float2 a, float2 b) {
    return make_float2(fminf(a.x, b.x), fminf(a.y, b.y));
}
__device__ __forceinline__ float2 fmax2(float2 a, float2 b) {
    return make_float2(fmaxf(a.x, b.x), fmaxf(a.y, b.y));
}

// out = relu(img - dilate3x3x3(erode3x3x3(img))), stride 1, pad 1.
// erode = min-pool (pad +inf), dilate = max-pool (pad -inf via domain mask).
// One thread per (float2-column, y) incl. halo; z marched with register rings.
// 4 small smem exchange rounds per plane (2 ping-pong buffers).
// Tuned for 4 blocks/SM: small blocks overlap each other's barrier bubbles.
__global__ __launch_bounds__(NTH, 4)
void soft_skel_kernel(const float* __restrict__ img, float* __restrict__ out) {
    __shared__ float2 sA[CH * CW];
    __shared__ float2 sB[CH * CW];

    const int tid = threadIdx.x;
    const int cx  = tid % CW;            // float2 column index
    const int iy  = tid / CW;            // row index (with halo)
    const int bx0 = blockIdx.x * TX;
    const int by0 = blockIdx.y * TY;
    const int bz  = blockIdx.z;
    const int b   = bz / ZCHUNKS;
    const int z0  = (bz % ZCHUNKS) * ZCK;
    const int z1  = z0 + ZCK;

    const int gx = bx0 + cx * 2 - 2;     // first element of the pair (even)
    const int gy = by0 + iy - 2;

    // pair is always fully inside or fully outside in x (gx even, X even)
    const bool inImg = (gx >= 0) && (gx < X) && (gy >= 0) && (gy < Y);
    const bool outP  = (iy >= 2) && (iy <= CH - 3) && (cx >= 1) && (cx <= CW - 2);

    // loop-invariant shared offsets (clamped at edges; the garbage a clamp
    // produces stays in the outermost shell and is never consumed)
    const int xl = (cx == 0)      ? 0      : cx - 1;
    const int xr = (cx == CW - 1) ? CW - 1 : cx + 1;
    const int yu = (iy == 0)      ? 0      : iy - 1;
    const int yd = (iy == CH - 1) ? CH - 1 : iy + 1;
    const int offC = iy * CW + cx;
    const int offL = iy * CW + xl;
    const int offR = iy * CW + xr;
    const int offU = yu * CW + cx;
    const int offD = yd * CW + cx;

    const float  PINF = __int_as_float(0x7f800000);
    const float  NINF = __int_as_float(0xff800000);
    const float2 PI2  = make_float2(PINF, PINF);

    const long base = (long)b * Z * YX + (long)gy * X + gx;
    const float* pIn = img + base + (long)(z0 - 1) * YX;   // next plane to load
    float*       pO  = out + base + (long)z0 * YX;

    // img ring: v0 = plane zi-2, v1 = zi-1, v2 = zi
    float2 v0 = PI2, v1 = PI2, v2;
    // erode ring: e0 = e(zi-3), e1 = e(zi-2)
    float2 e0 = make_float2(NINF, NINF), e1 = e0;

    // preload plane z0-2
    v2 = (inImg && (z0 - 2) >= 0) ? *(const float2*)(pIn - YX) : PI2;

    for (int zi = z0 - 2; zi <= z1 + 1; ++zi) {
        // ---- prefetch plane zi+1 (overlaps with this plane's compute)
        float2 vn = PI2;
        {
            const int zn = zi + 1;
            if (inImg && (unsigned)zn < (unsigned)Z)
                vn = *(const float2*)pIn;
            pIn += YX;
        }

        // ---- erode-z at plane zc = zi-1 (registers)
        float2 zm = fmin2(v0, fmin2(v1, v2));

        // ---- erode-y via smem (buffer A)
        sA[offC] = zm;
        __syncthreads();
        float2 yb = fmin2(sA[offU], fmin2(zm, sA[offD]));
        sB[offC] = yb;
        __syncthreads();

        // ---- erode-x (buffer B) + domain mask (-inf outside for dilate pad)
        {
            float2 L = sB[offL];
            float2 R = sB[offR];
            float ex = fminf(L.y, fminf(yb.x, yb.y));
            float ey = fminf(yb.x, fminf(yb.y, R.x));
            const int  zc = zi - 1;
            const bool vC = inImg && ((unsigned)zc < (unsigned)Z);
            float2 en;
            en.x = vC ? ex : NINF;
            en.y = vC ? ey : NINF;

            // ---- dilate-z at plane zo = zi-2 (registers)
            float2 dd = fmax2(e0, fmax2(e1, en));
            e0 = e1; e1 = en;

            // ---- dilate-y via smem (buffer A reusable after sync above)
            sA[offC] = dd;
            __syncthreads();
            float2 m = fmax2(sA[offU], fmax2(dd, sA[offD]));
            sB[offC] = m;
            __syncthreads();

            // ---- dilate-x + output: opened at plane zo = zi-2
            if (zi >= z0 + 2) {
                if (outP) {
                    float2 Lm = sB[offL];
                    float2 Rm = sB[offR];
                    float ox = fmaxf(Lm.y, fmaxf(m.x, m.y));
                    float oy = fmaxf(m.x, fmaxf(m.y, Rm.x));
                    float2 r;
                    r.x = fmaxf(v0.x - ox, 0.0f);   // v0 = img at plane zo
                    r.y = fmaxf(v0.y - oy, 0.0f);
                    *(float2*)pO = r;
                }
                pO += YX;
            }
        }

        // ---- shift img ring
        v0 = v1; v1 = v2; v2 = vn;
    }
}

extern "C" void kernel_launch(void* const* d_in, const int* in_sizes, int n_in,
                              void* d_out, int out_size) {
    (void)in_sizes; (void)n_in; (void)out_size;
    const float* img = (const float*)d_in[0];
    float* out = (float*)d_out;
    dim3 grid(X / TX, Y / TY, NB * ZCHUNKS);
    soft_skel_kernel<<<grid, NTH>>>(img, out);
}